// round 1
// baseline (speedup 1.0000x reference)
#include <cuda_runtime.h>
#include <cstdint>

// Problem constants (fixed by the dataset): B=4, n=4096/batch, C=20, NSAMPLE=32, R=2.
#define NS 32
#define MAXM 16384
#define TPB1 128
#define TPB2 128

// Scratch (device globals: allocation-free rule)
__device__ int g_idx[MAXM * NS];
__device__ int g_cnt[MAXM];

// ---------------------------------------------------------------------------
// Kernel 1: ball query. One thread per query point; the whole batch segment's
// xyz (48 KB) is staged in shared memory as 3 arrays (broadcast LDS reads).
// Semantics: first NS indices j (ascending) with d2 < r2; pad remaining slots
// with the first found index.
// ---------------------------------------------------------------------------
__global__ void ball_query_kernel(const float* __restrict__ xyz,
                                  const float* __restrict__ new_xyz,
                                  int n, float r2) {
    extern __shared__ float s[];
    float* sx = s;
    float* sy = s + n;
    float* sz = s + 2 * n;

    const int b = blockIdx.y;
    const float* seg = xyz + (size_t)b * n * 3;

    for (int j = threadIdx.x; j < n; j += blockDim.x) {
        sx[j] = seg[3 * j + 0];
        sy[j] = seg[3 * j + 1];
        sz[j] = seg[3 * j + 2];
    }
    __syncthreads();

    const int q = blockIdx.x * blockDim.x + threadIdx.x;
    if (q >= n) return;
    const int gi = b * n + q;

    const float qx = new_xyz[(size_t)gi * 3 + 0];
    const float qy = new_xyz[(size_t)gi * 3 + 1];
    const float qz = new_xyz[(size_t)gi * 3 + 2];

    int* out = g_idx + (size_t)gi * NS;
    int cnt = 0;

    for (int jb = 0; jb < n; jb += 16) {
#pragma unroll
        for (int u = 0; u < 16; u++) {
            const int j = jb + u;
            const float dx = __fadd_rn(sx[j], -qx);
            const float dy = __fadd_rn(sy[j], -qy);
            const float dz = __fadd_rn(sz[j], -qz);
            // Match reference rounding: (dx*dx + dy*dy) + dz*dz, no FMA fusion.
            const float d2 = __fadd_rn(__fadd_rn(__fmul_rn(dx, dx),
                                                 __fmul_rn(dy, dy)),
                                       __fmul_rn(dz, dz));
            if (d2 < r2 && cnt < NS) {
                out[cnt] = j;
                cnt++;
            }
        }
        if (cnt >= NS) break;
    }

    if (cnt == 0) {              // unreachable (query set == point set), defensive
        out[0] = q;
        cnt = 1;
    }
    // Pad with first index (padded slots DO contribute to grouped outputs).
    const int first = out[0];
    for (int k = cnt; k < NS; k++) out[k] = first;
    g_cnt[gi] = cnt;
}

// ---------------------------------------------------------------------------
// Kernel 2: gather rows into smem (coalesced 80B row loads), subtract the
// center feature, write the (C, NS)-transposed outputs contiguously, and emit
// weights. One block per query point.
// sp/st use stride C+1 = 21 (gcd(21,32)=1) -> conflict-free smem reads.
// ---------------------------------------------------------------------------
__global__ void group_kernel(const float* __restrict__ pred,
                             const float* __restrict__ tgt,
                             float* __restrict__ out_pred,
                             float* __restrict__ out_tgt,
                             float* __restrict__ out_w,
                             int n, int C) {
    const int i = blockIdx.x;
    const int t = threadIdx.x;
    const int CP = C + 1;  // padded smem stride

    __shared__ int   sidx[NS];
    __shared__ float sp[NS * 33];
    __shared__ float st[NS * 33];
    __shared__ float cp[32];
    __shared__ float ct[32];

    if (t < NS) sidx[t] = g_idx[(size_t)i * NS + t];
    if (t < C) {
        cp[t] = pred[(size_t)i * C + t];
        ct[t] = tgt[(size_t)i * C + t];
    }
    __syncthreads();

    const int base  = (i / n) * n;
    const int total = NS * C;

    for (int e = t; e < total; e += TPB2) {
        const int k = e / C;
        const int c = e - k * C;
        const size_t r = (size_t)(base + sidx[k]) * C + c;
        sp[k * CP + c] = pred[r];
        st[k * CP + c] = tgt[r];
    }
    __syncthreads();

    float* op = out_pred + (size_t)i * total;
    float* ot = out_tgt  + (size_t)i * total;
    for (int e = t; e < total; e += TPB2) {
        const int c = e / NS;
        const int k = e & (NS - 1);
        op[e] = sp[k * CP + c] - cp[c];
        ot[e] = st[k * CP + c] - ct[c];
    }

    if (t < NS) {
        const int cnt = g_cnt[i];
        out_w[(size_t)i * NS + t] = (t < cnt) ? (1.0f / (float)cnt) : 0.0f;
    }
}

// ---------------------------------------------------------------------------
// Launch. Inputs (metadata order): xyz, xyz_batch_cnt, pred, tgt, new_xyz,
// new_xyz_batch_cnt. Output: concat(pred_local (m,C,NS), tgt_local (m,C,NS),
// weight (m,NS)) as float32.
// ---------------------------------------------------------------------------
extern "C" void kernel_launch(void* const* d_in, const int* in_sizes, int n_in,
                              void* d_out, int out_size) {
    const float* xyz     = (const float*)d_in[0];
    const float* pred    = (const float*)d_in[2];
    const float* tgt     = (const float*)d_in[3];
    const float* new_xyz = (const float*)d_in[4];

    const int nb = in_sizes[1];                 // 4
    const int N  = in_sizes[0] / 3;             // 16384 total points
    const int n  = N / nb;                      // 4096 per batch
    const int C  = in_sizes[2] / N;             // 20
    const int m  = in_sizes[4] / 3;             // 16384 queries

    float* out_pred = (float*)d_out;
    float* out_tgt  = out_pred + (size_t)m * C * NS;
    float* out_w    = out_tgt  + (size_t)m * C * NS;

    const float r2 = 2.0f * 2.0f;

    dim3 grid1((n + TPB1 - 1) / TPB1, nb);
    const size_t smem1 = (size_t)3 * n * sizeof(float);  // 48 KB
    ball_query_kernel<<<grid1, TPB1, smem1>>>(xyz, new_xyz, n, r2);

    group_kernel<<<m, TPB2>>>(pred, tgt, out_pred, out_tgt, out_w, n, C);
}

// round 2
// speedup vs baseline: 1.7540x; 1.7540x over previous
#include <cuda_runtime.h>
#include <cstdint>

// Fixed dataset shape: B=4, n=4096/batch, C=20, NSAMPLE=32, R=2.
#define NS      32
#define CCH     20
#define SPLITS  8
#define NSEG    512          // 4096 / SPLITS
#define TPB1    128
#define NQB     256          // queries per ball-query block (2 per thread)
#define TPB2    160
#define MAXM    16384

typedef unsigned long long u64;

// Scratch (device globals: allocation-free rule).
__device__ int g_part[(size_t)MAXM * SPLITS * NS];
__device__ int g_pcnt[(size_t)MAXM * SPLITS];

// ---- packed f32x2 helpers (per-lane RN == scalar RN; bit-exact vs reference) ----
__device__ __forceinline__ u64 pk2(float a, float b) {
    u64 r; asm("mov.b64 %0, {%1, %2};" : "=l"(r) : "f"(a), "f"(b)); return r;
}
__device__ __forceinline__ u64 add2(u64 a, u64 b) {
    u64 r; asm("add.rn.f32x2 %0, %1, %2;" : "=l"(r) : "l"(a), "l"(b)); return r;
}
__device__ __forceinline__ u64 mul2(u64 a, u64 b) {
    u64 r; asm("mul.rn.f32x2 %0, %1, %2;" : "=l"(r) : "l"(a), "l"(b)); return r;
}
__device__ __forceinline__ void up2(u64 v, float& lo, float& hi) {
    asm("mov.b64 {%0, %1}, %2;" : "=f"(lo), "=f"(hi) : "l"(v));
}

// ---------------------------------------------------------------------------
// Kernel 1: split ball query. Block = (query tile of 256, split s, batch b).
// Each thread owns 2 queries; each iteration tests a packed pair of smem
// points against both queries. Per split: first-32 hits (ascending index)
// written to g_part; count to g_pcnt. Splits are index-ordered, so the merge
// is a truncated concat.
// ---------------------------------------------------------------------------
__global__ void __launch_bounds__(TPB1)
ball_query_kernel(const float* __restrict__ xyz,
                  const float* __restrict__ new_xyz,
                  int n, float r2) {
    __shared__ float sx[NSEG], sy[NSEG], sz[NSEG];

    const int b  = blockIdx.z;
    const int s  = blockIdx.y;
    const int j0 = s * NSEG;

    const float* seg = xyz + ((size_t)(b * n + j0)) * 3;
    for (int j = threadIdx.x; j < NSEG; j += TPB1) {
        sx[j] = seg[3 * j + 0];
        sy[j] = seg[3 * j + 1];
        sz[j] = seg[3 * j + 2];
    }
    __syncthreads();

    const int q0 = blockIdx.x * NQB + threadIdx.x;
    const int q1 = q0 + TPB1;
    const int g0 = b * n + q0;
    const int g1 = b * n + q1;

    // Negated query coords, broadcast into both packed halves.
    const u64 nqx0 = pk2(-new_xyz[3 * (size_t)g0 + 0], -new_xyz[3 * (size_t)g0 + 0]);
    const u64 nqy0 = pk2(-new_xyz[3 * (size_t)g0 + 1], -new_xyz[3 * (size_t)g0 + 1]);
    const u64 nqz0 = pk2(-new_xyz[3 * (size_t)g0 + 2], -new_xyz[3 * (size_t)g0 + 2]);
    const u64 nqx1 = pk2(-new_xyz[3 * (size_t)g1 + 0], -new_xyz[3 * (size_t)g1 + 0]);
    const u64 nqy1 = pk2(-new_xyz[3 * (size_t)g1 + 1], -new_xyz[3 * (size_t)g1 + 1]);
    const u64 nqz1 = pk2(-new_xyz[3 * (size_t)g1 + 2], -new_xyz[3 * (size_t)g1 + 2]);

    int c0 = 0, c1 = 0;
    int* o0 = g_part + ((size_t)g0 * SPLITS + s) * NS;
    int* o1 = g_part + ((size_t)g1 * SPLITS + s) * NS;

    const float2* px = (const float2*)sx;
    const float2* py = (const float2*)sy;
    const float2* pz = (const float2*)sz;

#pragma unroll 2
    for (int h = 0; h < NSEG / 2; h++) {
        const float2 fx = px[h];
        const float2 fy = py[h];
        const float2 fz = pz[h];
        const u64 X = pk2(fx.x, fx.y);
        const u64 Y = pk2(fy.x, fy.y);
        const u64 Z = pk2(fz.x, fz.y);
        const int j = j0 + 2 * h;

        {   // query 0: d2 = ((dx*dx + dy*dy) + dz*dz), RN per op, no FMA fusion
            const u64 dx = add2(X, nqx0);
            const u64 dy = add2(Y, nqy0);
            const u64 dz = add2(Z, nqz0);
            const u64 d2 = add2(add2(mul2(dx, dx), mul2(dy, dy)), mul2(dz, dz));
            float da, db; up2(d2, da, db);
            if (da < r2 && c0 < NS) { o0[c0] = j;     c0++; }
            if (db < r2 && c0 < NS) { o0[c0] = j + 1; c0++; }
        }
        {   // query 1
            const u64 dx = add2(X, nqx1);
            const u64 dy = add2(Y, nqy1);
            const u64 dz = add2(Z, nqz1);
            const u64 d2 = add2(add2(mul2(dx, dx), mul2(dy, dy)), mul2(dz, dz));
            float da, db; up2(d2, da, db);
            if (da < r2 && c1 < NS) { o1[c1] = j;     c1++; }
            if (db < r2 && c1 < NS) { o1[c1] = j + 1; c1++; }
        }
    }

    g_pcnt[(size_t)g0 * SPLITS + s] = c0;
    g_pcnt[(size_t)g1 * SPLITS + s] = c1;
}

// ---------------------------------------------------------------------------
// Kernel 2: merge partial lists (warp 0 prologue), gather rows as float4,
// transpose via padded smem, subtract center, vectorized stores + weights.
// One block per query. All index math uses compile-time C=20, NS=32.
// ---------------------------------------------------------------------------
__global__ void __launch_bounds__(TPB2)
group_kernel(const float* __restrict__ pred,
             const float* __restrict__ tgt,
             float* __restrict__ out_pred,
             float* __restrict__ out_tgt,
             float* __restrict__ out_w,
             int n) {
    const int i = blockIdx.x;
    const int t = threadIdx.x;

    __shared__ int   scnts[SPLITS];
    __shared__ int   sidx[NS];
    __shared__ int   stotal;
    __shared__ __align__(16) float sp[CCH][36];
    __shared__ __align__(16) float sg[CCH][36];
    __shared__ float cp[CCH], ct[CCH];

    if (t < SPLITS) scnts[t] = g_pcnt[(size_t)i * SPLITS + t];
    if (t < CCH) {
        cp[t] = pred[(size_t)i * CCH + t];
        ct[t] = tgt[(size_t)i * CCH + t];
    }
    __syncthreads();

    if (t < NS) {
        int acc = 0, src = 0, off = 0;
        bool found = false;
#pragma unroll
        for (int s2 = 0; s2 < SPLITS; s2++) {
            const int c = scnts[s2];
            if (!found && t < acc + c) { src = s2; off = t - acc; found = true; }
            acc += c;
        }
        const int total = acc < NS ? acc : NS;
        int v = 0;
        if (t < total) v = g_part[((size_t)i * SPLITS + src) * NS + off];
        sidx[t] = v;
        if (t == 0) stotal = total;
    }
    __syncthreads();
    if (t < NS && t >= stotal) sidx[t] = sidx[0];   // pad with first found index
    __syncthreads();

    const int base = (i / n) * n;

    // Gather: t -> (row k = t/5, quad qd = t%5); 80B rows are 16B-aligned.
    {
        const int k  = t / 5;
        const int qd = t - k * 5;
        const size_t r = ((size_t)(base + sidx[k])) * CCH + 4 * qd;
        const float4 vp = *(const float4*)(pred + r);
        const float4 vg = *(const float4*)(tgt + r);
        const int cc = 4 * qd;
        sp[cc + 0][k] = vp.x; sp[cc + 1][k] = vp.y;
        sp[cc + 2][k] = vp.z; sp[cc + 3][k] = vp.w;
        sg[cc + 0][k] = vg.x; sg[cc + 1][k] = vg.y;
        sg[cc + 2][k] = vg.z; sg[cc + 3][k] = vg.w;
    }
    __syncthreads();

    // Output: t -> (c = t>>3, k0 = (t&7)*4). LDS.128 + STG.128.
    {
        const int c  = t >> 3;
        const int k0 = (t & 7) * 4;

        float4 a = *(const float4*)&sp[c][k0];
        const float cv = cp[c];
        a.x -= cv; a.y -= cv; a.z -= cv; a.w -= cv;
        *(float4*)(out_pred + (size_t)i * (CCH * NS) + 4 * t) = a;

        float4 g2 = *(const float4*)&sg[c][k0];
        const float tv = ct[c];
        g2.x -= tv; g2.y -= tv; g2.z -= tv; g2.w -= tv;
        *(float4*)(out_tgt + (size_t)i * (CCH * NS) + 4 * t) = g2;
    }

    if (t < NS) {
        out_w[(size_t)i * NS + t] = (t < stotal) ? (1.0f / (float)stotal) : 0.0f;
    }
}

// ---------------------------------------------------------------------------
// Launch. Inputs: xyz, xyz_batch_cnt, pred, tgt, new_xyz, new_xyz_batch_cnt.
// Output: concat(pred_local (m,C,NS), tgt_local (m,C,NS), weight (m,NS)) f32.
// ---------------------------------------------------------------------------
extern "C" void kernel_launch(void* const* d_in, const int* in_sizes, int n_in,
                              void* d_out, int out_size) {
    const float* xyz     = (const float*)d_in[0];
    const float* pred    = (const float*)d_in[2];
    const float* tgt     = (const float*)d_in[3];
    const float* new_xyz = (const float*)d_in[4];

    const int nb = in_sizes[1];          // 4
    const int N  = in_sizes[0] / 3;      // 16384
    const int n  = N / nb;               // 4096
    const int m  = in_sizes[4] / 3;      // 16384

    float* out_pred = (float*)d_out;
    float* out_tgt  = out_pred + (size_t)m * CCH * NS;
    float* out_w    = out_tgt  + (size_t)m * CCH * NS;

    dim3 g1(n / NQB, SPLITS, nb);        // (16, 8, 4) = 512 blocks
    ball_query_kernel<<<g1, TPB1>>>(xyz, new_xyz, n, 4.0f);

    group_kernel<<<m, TPB2>>>(pred, tgt, out_pred, out_tgt, out_w, n);
}

// round 3
// speedup vs baseline: 2.3090x; 1.3164x over previous
#include <cuda_runtime.h>
#include <cstdint>

// Fixed dataset shape: B=4, n=4096/batch, C=20, NSAMPLE=32, R=2.
#define NS      32
#define CCH     20
#define SPLITS  16
#define NSEG    256          // 4096 / SPLITS
#define TPB1    128
#define NQB     256          // queries per ball-query block (2 per thread)
#define TPB2    256          // 8 warps -> 8 queries per block
#define MAXM    16384
#define FULL    0xFFFFFFFFu

typedef unsigned long long u64;

// Scratch (device globals: allocation-free rule). 16384*16*32*4 = 32 MB.
__device__ int g_part[(size_t)MAXM * SPLITS * NS];
__device__ int g_pcnt[(size_t)MAXM * SPLITS];

// ---- packed f32x2 helpers (per-lane RN == scalar RN; bit-exact vs reference) ----
__device__ __forceinline__ u64 pk2(float a, float b) {
    u64 r; asm("mov.b64 %0, {%1, %2};" : "=l"(r) : "f"(a), "f"(b)); return r;
}
__device__ __forceinline__ u64 add2(u64 a, u64 b) {
    u64 r; asm("add.rn.f32x2 %0, %1, %2;" : "=l"(r) : "l"(a), "l"(b)); return r;
}
__device__ __forceinline__ u64 mul2(u64 a, u64 b) {
    u64 r; asm("mul.rn.f32x2 %0, %1, %2;" : "=l"(r) : "l"(a), "l"(b)); return r;
}
__device__ __forceinline__ void up2(u64 v, float& lo, float& hi) {
    asm("mov.b64 {%0, %1}, %2;" : "=f"(lo), "=f"(hi) : "l"(v));
}

// ---------------------------------------------------------------------------
// Kernel 1: split ball query. Block = (query tile of 256, split s, batch b).
// Each thread owns 2 queries; each iteration tests a packed pair of smem
// points against both queries. Per split: first-32 hits (ascending index,
// local to batch) -> g_part; count -> g_pcnt.
// ---------------------------------------------------------------------------
__global__ void __launch_bounds__(TPB1)
ball_query_kernel(const float* __restrict__ xyz,
                  const float* __restrict__ new_xyz,
                  int n, float r2) {
    __shared__ float sx[NSEG], sy[NSEG], sz[NSEG];

    const int b  = blockIdx.z;
    const int s  = blockIdx.y;
    const int j0 = s * NSEG;

    const float* seg = xyz + ((size_t)(b * n + j0)) * 3;
    for (int j = threadIdx.x; j < NSEG; j += TPB1) {
        sx[j] = seg[3 * j + 0];
        sy[j] = seg[3 * j + 1];
        sz[j] = seg[3 * j + 2];
    }
    __syncthreads();

    const int q0 = blockIdx.x * NQB + threadIdx.x;
    const int q1 = q0 + TPB1;
    const int g0 = b * n + q0;
    const int g1 = b * n + q1;

    const float ax = new_xyz[3 * (size_t)g0 + 0];
    const float ay = new_xyz[3 * (size_t)g0 + 1];
    const float az = new_xyz[3 * (size_t)g0 + 2];
    const float bx = new_xyz[3 * (size_t)g1 + 0];
    const float by = new_xyz[3 * (size_t)g1 + 1];
    const float bz = new_xyz[3 * (size_t)g1 + 2];
    const u64 nqx0 = pk2(-ax, -ax), nqy0 = pk2(-ay, -ay), nqz0 = pk2(-az, -az);
    const u64 nqx1 = pk2(-bx, -bx), nqy1 = pk2(-by, -by), nqz1 = pk2(-bz, -bz);

    int c0 = 0, c1 = 0;
    int* o0 = g_part + ((size_t)g0 * SPLITS + s) * NS;
    int* o1 = g_part + ((size_t)g1 * SPLITS + s) * NS;

    const float2* px = (const float2*)sx;
    const float2* py = (const float2*)sy;
    const float2* pz = (const float2*)sz;

#pragma unroll 4
    for (int h = 0; h < NSEG / 2; h++) {
        const float2 fx = px[h];
        const float2 fy = py[h];
        const float2 fz = pz[h];
        const u64 X = pk2(fx.x, fx.y);
        const u64 Y = pk2(fy.x, fy.y);
        const u64 Z = pk2(fz.x, fz.y);
        const int j = j0 + 2 * h;

        {   // query 0: d2 = ((dx*dx + dy*dy) + dz*dz), RN per op, no FMA fusion
            const u64 dx = add2(X, nqx0);
            const u64 dy = add2(Y, nqy0);
            const u64 dz = add2(Z, nqz0);
            const u64 d2 = add2(add2(mul2(dx, dx), mul2(dy, dy)), mul2(dz, dz));
            float da, db; up2(d2, da, db);
            if (da < r2 && c0 < NS) { o0[c0] = j;     c0++; }
            if (db < r2 && c0 < NS) { o0[c0] = j + 1; c0++; }
        }
        {   // query 1
            const u64 dx = add2(X, nqx1);
            const u64 dy = add2(Y, nqy1);
            const u64 dz = add2(Z, nqz1);
            const u64 d2 = add2(add2(mul2(dx, dx), mul2(dy, dy)), mul2(dz, dz));
            float da, db; up2(d2, da, db);
            if (da < r2 && c1 < NS) { o1[c1] = j;     c1++; }
            if (db < r2 && c1 < NS) { o1[c1] = j + 1; c1++; }
        }
    }

    g_pcnt[(size_t)g0 * SPLITS + s] = c0;
    g_pcnt[(size_t)g1 * SPLITS + s] = c1;
}

// ---------------------------------------------------------------------------
// Kernel 2: warp-per-query. No shared memory, no barriers.
//   - merge split lists via shuffle prefix-sum (lane k -> (src,off))
//   - lane k holds the full gathered rows (pred+tgt) in registers
//   - transpose through the register file: out row c = r[c] - shfl(center, c),
//     stored as one coalesced STG.32 per channel.
// ---------------------------------------------------------------------------
__global__ void __launch_bounds__(TPB2)
group_kernel(const float* __restrict__ pred,
             const float* __restrict__ tgt,
             float* __restrict__ out_pred,
             float* __restrict__ out_tgt,
             float* __restrict__ out_w,
             int n) {
    const int w    = threadIdx.x >> 5;
    const int lane = threadIdx.x & 31;
    const int i    = blockIdx.x * (TPB2 / 32) + w;   // query id

    // --- merge: counts in lanes 0..15, inclusive prefix-sum across warp ---
    int p = (lane < SPLITS) ? g_pcnt[(size_t)i * SPLITS + lane] : 0;
#pragma unroll
    for (int d = 1; d < 32; d <<= 1) {
        int v = __shfl_up_sync(FULL, p, d);
        if (lane >= d) p += v;
    }
    int total = __shfl_sync(FULL, p, SPLITS - 1);
    if (total > NS) total = NS;

    // lane k: source split = #prefixes <= k; off = k - excl_prefix(src)
    int src = 0, pe = 0;
#pragma unroll
    for (int s = 0; s < SPLITS; s++) {
        const int ps = __shfl_sync(FULL, p, s);
        if (lane >= ps) { src = s + 1; pe = ps; }
    }
    int idx = 0;
    if (lane < total) idx = g_part[((size_t)i * SPLITS + src) * NS + (lane - pe)];
    const int first = __shfl_sync(FULL, idx, 0);     // lane 0 always valid (self-hit)
    if (lane >= total) idx = first;                  // pad with first found index

    // --- gather: lane k owns row idx[k] of both feature arrays ---
    const int row = (i / n) * n + idx;
    const float4* pr = (const float4*)(pred + (size_t)row * CCH);
    const float4* gr = (const float4*)(tgt  + (size_t)row * CCH);
    float4 rp[5], rg[5];
#pragma unroll
    for (int j = 0; j < 5; j++) rp[j] = pr[j];
#pragma unroll
    for (int j = 0; j < 5; j++) rg[j] = gr[j];

    // center features (lane c < 20 holds channel c)
    const float cpv = (lane < CCH) ? pred[(size_t)i * CCH + lane] : 0.0f;
    const float ctv = (lane < CCH) ? tgt [(size_t)i * CCH + lane] : 0.0f;

    // --- register-file transpose + subtract + coalesced stores ---
    const float* fp = (const float*)rp;
    const float* fg = (const float*)rg;
    float* op = out_pred + (size_t)i * (CCH * NS);
    float* ot = out_tgt  + (size_t)i * (CCH * NS);
#pragma unroll
    for (int c = 0; c < CCH; c++) {
        op[c * NS + lane] = fp[c] - __shfl_sync(FULL, cpv, c);
        ot[c * NS + lane] = fg[c] - __shfl_sync(FULL, ctv, c);
    }

    out_w[(size_t)i * NS + lane] = (lane < total) ? (1.0f / (float)total) : 0.0f;
}

// ---------------------------------------------------------------------------
// Launch. Inputs: xyz, xyz_batch_cnt, pred, tgt, new_xyz, new_xyz_batch_cnt.
// Output: concat(pred_local (m,C,NS), tgt_local (m,C,NS), weight (m,NS)) f32.
// ---------------------------------------------------------------------------
extern "C" void kernel_launch(void* const* d_in, const int* in_sizes, int n_in,
                              void* d_out, int out_size) {
    const float* xyz     = (const float*)d_in[0];
    const float* pred    = (const float*)d_in[2];
    const float* tgt     = (const float*)d_in[3];
    const float* new_xyz = (const float*)d_in[4];

    const int nb = in_sizes[1];          // 4
    const int N  = in_sizes[0] / 3;      // 16384
    const int n  = N / nb;               // 4096
    const int m  = in_sizes[4] / 3;      // 16384

    float* out_pred = (float*)d_out;
    float* out_tgt  = out_pred + (size_t)m * CCH * NS;
    float* out_w    = out_tgt  + (size_t)m * CCH * NS;

    dim3 g1(n / NQB, SPLITS, nb);        // (16, 16, 4) = 1024 blocks
    ball_query_kernel<<<g1, TPB1>>>(xyz, new_xyz, n, 4.0f);

    group_kernel<<<m / (TPB2 / 32), TPB2>>>(pred, tgt, out_pred, out_tgt, out_w, n);
}